// round 3
// baseline (speedup 1.0000x reference)
#include <cuda_runtime.h>
#include <cstdint>

// ---------------------------------------------------------------------------
// GCN: 4 conv layers + global max pool + MLP.
//   norm precompute (deg -> rsqrt -> edge norm)
//   layer1: propagate x (1 feat/edge), fuse (Ax)*W1+b1 expansion into layer2 GEMM
//   layers 2-4: GEMM (h@W) first, then scatter fo features with red.global.v4
//   self-loop term dis^2*t fused into GEMM epilogue
//   bias+relu fused into next GEMM's staging loads
//   pool: sorted-batch running max + sparse atomicMax
// R2 fix: harness may downcast int64 inputs (edge_index, batch) to int32.
// Detect dtype on-device (odd 32-bit words all zero <=> int64) and branch.
// ---------------------------------------------------------------------------

constexpr int NN = 100000;
constexpr int EE = 1600000;
constexpr int GG = 64;

__device__ __align__(16) float g_deg[NN];            // deg, then dis (in place)
__device__ __align__(16) float g_norm[EE];
__device__ __align__(16) int   g_src[EE];
__device__ __align__(16) int   g_dst[EE];
__device__ __align__(16) float g_ax[NN];
__device__ __align__(16) float g_A[(size_t)NN * 128];
__device__ __align__(16) float g_B[(size_t)NN * 128];
__device__ __align__(16) float g_C[(size_t)NN * 128];
__device__ __align__(16) float g_pool[GG * 32];
__device__ int g_is64;

__device__ __forceinline__ void red_add_f32(float* p, float v) {
    asm volatile("red.global.add.f32 [%0], %1;" :: "l"(p), "f"(v) : "memory");
}
__device__ __forceinline__ void red_add_v4(float* p, float4 v) {
    asm volatile("red.global.add.v4.f32 [%0], {%1,%2,%3,%4};"
                 :: "l"(p), "f"(v.x), "f"(v.y), "f"(v.z), "f"(v.w) : "memory");
}

// ---------------- dtype detection ----------------
// If edge_index is int64 (values < 2^31, non-negative), every odd 32-bit word
// is 0. If int32, odd words are random node ids (can't all be 0 over 2048).
__global__ void k_detect(const int* __restrict__ raw) {
    __shared__ int any;
    if (threadIdx.x == 0) any = 0;
    __syncthreads();
    int v = 0;
    for (int k = threadIdx.x; k < 2048; k += blockDim.x) v |= raw[2 * k + 1];
    if (v) atomicOr(&any, 1);
    __syncthreads();
    if (threadIdx.x == 0) g_is64 = (any == 0) ? 1 : 0;
}

// ---------------- norm precompute ----------------

__global__ void k_init_deg(int n) {
    int i = blockIdx.x * blockDim.x + threadIdx.x;
    if (i < n) g_deg[i] = 1.0f;   // self loop weight
}

__global__ void k_edges_pre(const void* __restrict__ ei,
                            const float* __restrict__ w, int e) {
    int i = blockIdx.x * blockDim.x + threadIdx.x;
    if (i >= e) return;
    int s, d;
    if (g_is64) {
        const long long* p = (const long long*)ei;
        s = (int)p[i];
        d = (int)p[(size_t)e + i];
    } else {
        const int* p = (const int*)ei;
        s = p[i];
        d = p[e + i];
    }
    g_src[i] = s;
    g_dst[i] = d;
    atomicAdd(&g_deg[d], w[i]);
}

__global__ void k_dis(int n) {
    int i = blockIdx.x * blockDim.x + threadIdx.x;
    if (i < n) {
        float dg = g_deg[i];
        g_deg[i] = (dg > 0.f) ? rsqrtf(dg) : 0.f;
    }
}

__global__ void k_norm(const float* __restrict__ w, int e) {
    int i = blockIdx.x * blockDim.x + threadIdx.x;
    if (i < e) g_norm[i] = g_deg[g_src[i]] * w[i] * g_deg[g_dst[i]];
}

// ---------------- layer 1: propagate x ----------------

__global__ void k_ax_init(const float* __restrict__ x, int n) {
    int i = blockIdx.x * blockDim.x + threadIdx.x;
    if (i < n) {
        float d = g_deg[i];
        g_ax[i] = d * d * x[i];
    }
}

__global__ void k_ax_scatter(const float* __restrict__ x, int e) {
    int i = blockIdx.x * blockDim.x + threadIdx.x;
    if (i >= e) return;
    red_add_f32(&g_ax[g_dst[i]], g_norm[i] * x[g_src[i]]);
}

// ---------------- layer 2 GEMM (fused layer-1 expand): FI=128, FO=96 --------
// h1[node][k] = relu(ax[node]*W1[k] + b1[k]) computed on the fly.
// Writes t2 -> tbuf, dis^2*t2 -> obuf.

__global__ __launch_bounds__(128)
void k_gemm2(const float* __restrict__ W1, const float* __restrict__ b1,
             const float* __restrict__ W2,
             float* __restrict__ tbuf, float* __restrict__ obuf, int n) {
    __shared__ __align__(16) float W1s[128];
    __shared__ __align__(16) float b1s[128];
    __shared__ __align__(16) float Ws[128 * 32];
    const int tid = threadIdx.x;
    const int fo0 = blockIdx.y * 32;
    const int n0 = blockIdx.x * 64;

    W1s[tid] = W1[tid];
    b1s[tid] = b1[tid];
    for (int i = tid; i < 128 * 32; i += 128) {
        int k = i >> 5, j = i & 31;
        Ws[i] = W2[k * 96 + fo0 + j];
    }
    const int fo_t = tid & 7;     // 8 groups of 4 fo
    const int nd_t = tid >> 3;    // 16 groups of 4 nodes
    float axv[4];
#pragma unroll
    for (int i = 0; i < 4; i++) {
        int nd = n0 + nd_t * 4 + i;
        axv[i] = (nd < n) ? g_ax[nd] : 0.f;
    }
    __syncthreads();

    float acc[4][4] = {};
#pragma unroll 8
    for (int k = 0; k < 128; k++) {
        float w1 = W1s[k], bb = b1s[k];
        float4 w = *reinterpret_cast<const float4*>(Ws + k * 32 + fo_t * 4);
#pragma unroll
        for (int i = 0; i < 4; i++) {
            float h = fmaxf(fmaf(axv[i], w1, bb), 0.f);
            acc[i][0] = fmaf(h, w.x, acc[i][0]);
            acc[i][1] = fmaf(h, w.y, acc[i][1]);
            acc[i][2] = fmaf(h, w.z, acc[i][2]);
            acc[i][3] = fmaf(h, w.w, acc[i][3]);
        }
    }
#pragma unroll
    for (int i = 0; i < 4; i++) {
        int nd = n0 + nd_t * 4 + i;
        if (nd >= n) continue;
        float d = g_deg[nd];
        float d2 = d * d;
        size_t off = (size_t)nd * 96 + fo0 + fo_t * 4;
        float4 tv = make_float4(acc[i][0], acc[i][1], acc[i][2], acc[i][3]);
        float4 ov = make_float4(d2 * tv.x, d2 * tv.y, d2 * tv.z, d2 * tv.w);
        *reinterpret_cast<float4*>(tbuf + off) = tv;
        *reinterpret_cast<float4*>(obuf + off) = ov;
    }
}

// ---------------- generic GEMM layers 3,4: relu(in+bias) @ W ----------------

template <int FI, int FO>
__global__ __launch_bounds__(128)
void k_gemm(const float* __restrict__ hin, const float* __restrict__ bin,
            const float* __restrict__ W,
            float* __restrict__ tbuf, float* __restrict__ obuf, int n) {
    __shared__ __align__(16) float hsT[FI * 65];      // [k][node], stride 65 (pad)
    __shared__ __align__(16) float Ws[FI * 32];
    __shared__ __align__(16) float bs[FI];
    const int tid = threadIdx.x;
    const int fo0 = blockIdx.y * 32;
    const int n0 = blockIdx.x * 64;

    for (int i = tid; i < FI; i += 128) bs[i] = bin[i];
    for (int i = tid; i < FI * 32; i += 128) {
        int k = i >> 5, j = i & 31;
        Ws[i] = W[k * FO + fo0 + j];
    }
    __syncthreads();
    for (int i = tid; i < 64 * FI; i += 128) {
        int node = i / FI, k = i % FI;
        int gn = n0 + node;
        float v = 0.f;
        if (gn < n) v = fmaxf(hin[(size_t)gn * FI + k] + bs[k], 0.f);
        hsT[k * 65 + node] = v;
    }
    __syncthreads();

    const int fo_t = tid & 7;
    const int nd_t = tid >> 3;
    float acc[4][4] = {};
#pragma unroll 8
    for (int k = 0; k < FI; k++) {
        float4 w = *reinterpret_cast<const float4*>(Ws + k * 32 + fo_t * 4);
        const float* hr = hsT + k * 65 + nd_t * 4;
#pragma unroll
        for (int i = 0; i < 4; i++) {
            float h = hr[i];
            acc[i][0] = fmaf(h, w.x, acc[i][0]);
            acc[i][1] = fmaf(h, w.y, acc[i][1]);
            acc[i][2] = fmaf(h, w.z, acc[i][2]);
            acc[i][3] = fmaf(h, w.w, acc[i][3]);
        }
    }
#pragma unroll
    for (int i = 0; i < 4; i++) {
        int nd = n0 + nd_t * 4 + i;
        if (nd >= n) continue;
        float d = g_deg[nd];
        float d2 = d * d;
        size_t off = (size_t)nd * FO + fo0 + fo_t * 4;
        float4 tv = make_float4(acc[i][0], acc[i][1], acc[i][2], acc[i][3]);
        float4 ov = make_float4(d2 * tv.x, d2 * tv.y, d2 * tv.z, d2 * tv.w);
        *reinterpret_cast<float4*>(tbuf + off) = tv;
        *reinterpret_cast<float4*>(obuf + off) = ov;
    }
}

// ---------------- edge scatter: out[dst] += norm * t[src] ----------------

template <int FO>
__global__ __launch_bounds__(256)
void k_scatter(const float* __restrict__ t, float* __restrict__ out, int e) {
    constexpr int FO4 = FO / 4;
    int idx = blockIdx.x * blockDim.x + threadIdx.x;
    if (idx >= e * FO4) return;
    int ed = idx / FO4;
    int c = idx - ed * FO4;
    int s = g_src[ed];
    int d = g_dst[ed];
    float nm = g_norm[ed];
    float4 v = *reinterpret_cast<const float4*>(t + (size_t)s * FO + c * 4);
    v.x *= nm; v.y *= nm; v.z *= nm; v.w *= nm;
    red_add_v4(out + (size_t)d * FO + c * 4, v);
}

// ---------------- pooling ----------------

__global__ void k_zero_pool() {
    int i = blockIdx.x * blockDim.x + threadIdx.x;
    if (i < GG * 32) g_pool[i] = 0.f;
}

// block (32,8), each block covers 2048 nodes; batch sorted -> running max
__global__ void k_pool(const float* __restrict__ h, const float* __restrict__ b4,
                       const void* __restrict__ batch, int n) {
    const int tx = threadIdx.x;   // feature lane
    const int ty = threadIdx.y;   // node row
    const int base = blockIdx.x * 2048;
    const float bb = __ldg(&b4[tx]);
    const int is64 = g_is64;
    const long long* b64 = (const long long*)batch;
    const int* b32 = (const int*)batch;
    float rmax = 0.f;
    int curg = -1;
    for (int off = ty; off < 2048; off += 8) {
        int nd = base + off;
        if (nd >= n) break;
        int g = is64 ? (int)b64[nd] : b32[nd];
        float v = fmaxf(h[(size_t)nd * 32 + tx] + bb, 0.f);
        if (g != curg) {
            if (curg >= 0)
                atomicMax(reinterpret_cast<int*>(&g_pool[curg * 32 + tx]),
                          __float_as_int(rmax));
            curg = g;
            rmax = v;
        } else {
            rmax = fmaxf(rmax, v);
        }
    }
    if (curg >= 0)
        atomicMax(reinterpret_cast<int*>(&g_pool[curg * 32 + tx]),
                  __float_as_int(rmax));
}

// ---------------- final MLP: relu(g@W5+b5)@W6+b6 ----------------

__global__ void k_mlp(const float* __restrict__ W5, const float* __restrict__ b5,
                      const float* __restrict__ W6, const float* __restrict__ b6,
                      float* __restrict__ out) {
    __shared__ float W5s[32 * 32], b5s[32], W6s[64], b6s[2];
    int t = threadIdx.x;   // 64 threads = 64 graphs
    for (int i = t; i < 1024; i += 64) W5s[i] = W5[i];
    if (t < 32) b5s[t] = b5[t];
    W6s[t] = W6[t];
    if (t < 2) b6s[t] = b6[t];
    __syncthreads();
    float p[32];
#pragma unroll
    for (int k = 0; k < 32; k++) p[k] = g_pool[t * 32 + k];
    float o0 = b6s[0], o1 = b6s[1];
#pragma unroll 4
    for (int j = 0; j < 32; j++) {
        float s = b5s[j];
#pragma unroll
        for (int k = 0; k < 32; k++) s = fmaf(p[k], W5s[k * 32 + j], s);
        s = fmaxf(s, 0.f);
        o0 = fmaf(s, W6s[j * 2], o0);
        o1 = fmaf(s, W6s[j * 2 + 1], o1);
    }
    out[t * 2] = o0;
    out[t * 2 + 1] = o1;
}

// ---------------- launch ----------------

extern "C" void kernel_launch(void* const* d_in, const int* in_sizes, int n_in,
                              void* d_out, int out_size) {
    const float* x  = (const float*)d_in[0];
    const void*  ei = d_in[1];
    const float* ew = (const float*)d_in[2];
    const void*  bt = d_in[3];
    const float* W1 = (const float*)d_in[4];
    const float* b1 = (const float*)d_in[5];
    const float* W2 = (const float*)d_in[6];
    const float* b2 = (const float*)d_in[7];
    const float* W3 = (const float*)d_in[8];
    const float* b3 = (const float*)d_in[9];
    const float* W4 = (const float*)d_in[10];
    const float* b4 = (const float*)d_in[11];
    const float* W5 = (const float*)d_in[12];
    const float* b5 = (const float*)d_in[13];
    const float* W6 = (const float*)d_in[14];
    const float* b6 = (const float*)d_in[15];
    float* out = (float*)d_out;

    const int n = in_sizes[0];
    const int e = in_sizes[2];

    const int nb = (n + 255) / 256;
    const int ebk = (e + 255) / 256;

    k_detect<<<1, 256>>>((const int*)ei);
    k_init_deg<<<nb, 256>>>(n);
    k_edges_pre<<<ebk, 256>>>(ei, ew, e);
    k_dis<<<nb, 256>>>(n);
    k_norm<<<ebk, 256>>>(ew, e);

    // layer 1: propagate x
    k_ax_init<<<nb, 256>>>(x, n);
    k_ax_scatter<<<ebk, 256>>>(x, e);

    const int gx = (n + 63) / 64;

    float* A; float* B; float* C;
    cudaGetSymbolAddress((void**)&A, g_A);
    cudaGetSymbolAddress((void**)&B, g_B);
    cudaGetSymbolAddress((void**)&C, g_C);

    // layer 2 (fused layer-1 expand): t2->B, out2init->C, then scatter into C
    k_gemm2<<<dim3(gx, 3), 128>>>(W1, b1, W2, B, C, n);
    k_scatter<96><<<(e * 24 + 255) / 256, 256>>>(B, C, e);

    // layer 3: in C (+b2,relu) -> t3->A, out3init->B, scatter into B
    k_gemm<96, 64><<<dim3(gx, 2), 128>>>(C, b2, W3, A, B, n);
    k_scatter<64><<<(e * 16 + 255) / 256, 256>>>(A, B, e);

    // layer 4: in B (+b3,relu) -> t4->C, out4init->A, scatter into A
    k_gemm<64, 32><<<dim3(gx, 1), 128>>>(B, b3, W4, C, A, n);
    k_scatter<32><<<(e * 8 + 255) / 256, 256>>>(C, A, e);

    // pool + MLP
    k_zero_pool<<<8, 256>>>();
    k_pool<<<(n + 2047) / 2048, dim3(32, 8)>>>(A, b4, bt, n);
    k_mlp<<<1, 64>>>(W5, b5, W6, b6, out);
}

// round 4
// speedup vs baseline: 1.4280x; 1.4280x over previous
#include <cuda_runtime.h>
#include <cstdint>

// ---------------------------------------------------------------------------
// GCN: 4 conv layers + global max pool + MLP.
// R4: replace all red.global scatters with CSR(dst) gathers (no atomics in the
// hot path), fold self-loop term into gather (GEMMs write one buffer only).
//   layer1: gather x (1 feat/edge), fuse (Ax)*W1+b1 expansion into layer2 GEMM
//   layers 2-4: GEMM (h@W) first, then per-dst gather of fo features
//   bias+relu fused into next GEMM's staging loads
//   pool: sorted-batch running max + sparse atomicMax
// ---------------------------------------------------------------------------

constexpr int NN = 100000;
constexpr int EE = 1600000;
constexpr int GG = 64;

__device__ __align__(16) float g_deg[NN];            // deg, then dis (in place)
__device__ __align__(16) int   g_src[EE];
__device__ __align__(16) int   g_dst[EE];
__device__ __align__(16) int   g_csrc[EE];           // CSR: src sorted by dst
__device__ __align__(16) float g_cnorm[EE];          // CSR: norm sorted by dst
__device__ __align__(16) int   g_off[NN + 1];
__device__ __align__(16) int   g_cnt[NN];
__device__ __align__(16) int   g_cur[NN];
__device__ __align__(16) int   g_aux[128];
__device__ __align__(16) float g_ax[NN];
__device__ __align__(16) float g_A[(size_t)NN * 128];
__device__ __align__(16) float g_B[(size_t)NN * 128];
__device__ __align__(16) float g_C[(size_t)NN * 128];
__device__ __align__(16) float g_pool[GG * 32];
__device__ int g_is64;

// ---------------- dtype detection ----------------
// int64 node ids < 2^31 => every odd 32-bit word is 0. int32 => random ids.
__global__ void k_detect(const int* __restrict__ raw) {
    __shared__ int any;
    if (threadIdx.x == 0) any = 0;
    __syncthreads();
    int v = 0;
    for (int k = threadIdx.x; k < 2048; k += blockDim.x) v |= raw[2 * k + 1];
    if (v) atomicOr(&any, 1);
    __syncthreads();
    if (threadIdx.x == 0) g_is64 = (any == 0) ? 1 : 0;
}

// ---------------- init + degree/count ----------------

__global__ void k_init(int n) {
    int i = blockIdx.x * blockDim.x + threadIdx.x;
    if (i < n) {
        g_deg[i] = 1.0f;   // self loop weight
        g_cnt[i] = 0;
        g_cur[i] = 0;
    }
}

__global__ void k_edges_pre(const void* __restrict__ ei,
                            const float* __restrict__ w, int e) {
    int i = blockIdx.x * blockDim.x + threadIdx.x;
    if (i >= e) return;
    int s, d;
    if (g_is64) {
        const long long* p = (const long long*)ei;
        s = (int)p[i];
        d = (int)p[(size_t)e + i];
    } else {
        const int* p = (const int*)ei;
        s = p[i];
        d = p[e + i];
    }
    g_src[i] = s;
    g_dst[i] = d;
    atomicAdd(&g_deg[d], w[i]);
    atomicAdd(&g_cnt[d], 1);
}

// ---------------- exclusive scan of g_cnt -> g_off (3 kernels) ----------------

__global__ void k_scan1(int n) {   // 1024 threads/block, chunk=1024
    __shared__ int s[1024];
    int t = threadIdx.x;
    int base = blockIdx.x * 1024;
    int v = (base + t < n) ? g_cnt[base + t] : 0;
    s[t] = v;
    __syncthreads();
    for (int d = 1; d < 1024; d <<= 1) {
        int x = (t >= d) ? s[t - d] : 0;
        __syncthreads();
        s[t] += x;
        __syncthreads();
    }
    if (base + t < n) g_off[base + t + 1] = s[t];   // inclusive within chunk
    if (t == 1023) g_aux[blockIdx.x] = s[1023];
}

__global__ void k_scan2(int naux) {  // single block, 1024 threads
    __shared__ int s[1024];
    int t = threadIdx.x;
    s[t] = (t < naux) ? g_aux[t] : 0;
    __syncthreads();
    for (int d = 1; d < 1024; d <<= 1) {
        int x = (t >= d) ? s[t - d] : 0;
        __syncthreads();
        s[t] += x;
        __syncthreads();
    }
    if (t < naux) g_aux[t] = (t > 0) ? s[t - 1] : 0;   // exclusive chunk bases
}

__global__ void k_scan3(int n) {
    int i = blockIdx.x * blockDim.x + threadIdx.x;
    if (i < n) g_off[i + 1] += g_aux[i >> 10];
    if (i == 0) g_off[0] = 0;
}

// ---------------- dis + norm + CSR fill ----------------

__global__ void k_dis(int n) {
    int i = blockIdx.x * blockDim.x + threadIdx.x;
    if (i < n) {
        float dg = g_deg[i];
        g_deg[i] = (dg > 0.f) ? rsqrtf(dg) : 0.f;
    }
}

__global__ void k_norm_fill(const float* __restrict__ w, int e) {
    int i = blockIdx.x * blockDim.x + threadIdx.x;
    if (i >= e) return;
    int s = g_src[i];
    int d = g_dst[i];
    float nm = g_deg[s] * w[i] * g_deg[d];
    int pos = g_off[d] + atomicAdd(&g_cur[d], 1);
    g_csrc[pos] = s;
    g_cnorm[pos] = nm;
}

// ---------------- layer 1: gather x ----------------

__global__ void k_gather_ax(const float* __restrict__ x, int n) {
    int i = blockIdx.x * blockDim.x + threadIdx.x;
    if (i >= n) return;
    float d = g_deg[i];
    float acc = d * d * x[i];
    int r0 = g_off[i], r1 = g_off[i + 1];
    for (int j = r0; j < r1; j++)
        acc = fmaf(g_cnorm[j], x[g_csrc[j]], acc);
    g_ax[i] = acc;
}

// ---------------- layer 2 GEMM (fused layer-1 expand): FI=128, FO=96 --------
// h1[node][k] = relu(ax[node]*W1[k] + b1[k]) computed on the fly.

__global__ __launch_bounds__(128)
void k_gemm2(const float* __restrict__ W1, const float* __restrict__ b1,
             const float* __restrict__ W2,
             float* __restrict__ tbuf, int n) {
    __shared__ __align__(16) float W1s[128];
    __shared__ __align__(16) float b1s[128];
    __shared__ __align__(16) float Ws[128 * 32];
    const int tid = threadIdx.x;
    const int fo0 = blockIdx.y * 32;
    const int n0 = blockIdx.x * 64;

    W1s[tid] = W1[tid];
    b1s[tid] = b1[tid];
    for (int i = tid; i < 128 * 32; i += 128) {
        int k = i >> 5, j = i & 31;
        Ws[i] = W2[k * 96 + fo0 + j];
    }
    const int fo_t = tid & 7;     // 8 groups of 4 fo
    const int nd_t = tid >> 3;    // 16 groups of 4 nodes
    float axv[4];
#pragma unroll
    for (int i = 0; i < 4; i++) {
        int nd = n0 + nd_t * 4 + i;
        axv[i] = (nd < n) ? g_ax[nd] : 0.f;
    }
    __syncthreads();

    float acc[4][4] = {};
#pragma unroll 8
    for (int k = 0; k < 128; k++) {
        float w1 = W1s[k], bb = b1s[k];
        float4 w = *reinterpret_cast<const float4*>(Ws + k * 32 + fo_t * 4);
#pragma unroll
        for (int i = 0; i < 4; i++) {
            float h = fmaxf(fmaf(axv[i], w1, bb), 0.f);
            acc[i][0] = fmaf(h, w.x, acc[i][0]);
            acc[i][1] = fmaf(h, w.y, acc[i][1]);
            acc[i][2] = fmaf(h, w.z, acc[i][2]);
            acc[i][3] = fmaf(h, w.w, acc[i][3]);
        }
    }
#pragma unroll
    for (int i = 0; i < 4; i++) {
        int nd = n0 + nd_t * 4 + i;
        if (nd >= n) continue;
        size_t off = (size_t)nd * 96 + fo0 + fo_t * 4;
        *reinterpret_cast<float4*>(tbuf + off) =
            make_float4(acc[i][0], acc[i][1], acc[i][2], acc[i][3]);
    }
}

// ---------------- generic GEMM layers 3,4: relu(in+bias) @ W ----------------

template <int FI, int FO>
__global__ __launch_bounds__(128)
void k_gemm(const float* __restrict__ hin, const float* __restrict__ bin,
            const float* __restrict__ W,
            float* __restrict__ tbuf, int n) {
    constexpr int FI4 = FI / 4;
    __shared__ __align__(16) float hsT[FI * 65];      // [k][node], stride 65 (pad)
    __shared__ __align__(16) float Ws[FI * 32];
    __shared__ __align__(16) float bs[FI];
    const int tid = threadIdx.x;
    const int fo0 = blockIdx.y * 32;
    const int n0 = blockIdx.x * 64;

    for (int i = tid; i < FI; i += 128) bs[i] = bin[i];
    for (int i = tid; i < FI * 32; i += 128) {
        int k = i >> 5, j = i & 31;
        Ws[i] = W[k * FO + fo0 + j];
    }
    __syncthreads();
    for (int i = tid; i < 64 * FI4; i += 128) {
        int node = i / FI4, c = i % FI4;
        int gn = n0 + node;
        float4 v = make_float4(0.f, 0.f, 0.f, 0.f);
        if (gn < n) {
            float4 r = *reinterpret_cast<const float4*>(hin + (size_t)gn * FI + c * 4);
            v.x = fmaxf(r.x + bs[c * 4 + 0], 0.f);
            v.y = fmaxf(r.y + bs[c * 4 + 1], 0.f);
            v.z = fmaxf(r.z + bs[c * 4 + 2], 0.f);
            v.w = fmaxf(r.w + bs[c * 4 + 3], 0.f);
        }
        hsT[(c * 4 + 0) * 65 + node] = v.x;
        hsT[(c * 4 + 1) * 65 + node] = v.y;
        hsT[(c * 4 + 2) * 65 + node] = v.z;
        hsT[(c * 4 + 3) * 65 + node] = v.w;
    }
    __syncthreads();

    const int fo_t = tid & 7;
    const int nd_t = tid >> 3;
    float acc[4][4] = {};
#pragma unroll 8
    for (int k = 0; k < FI; k++) {
        float4 w = *reinterpret_cast<const float4*>(Ws + k * 32 + fo_t * 4);
        const float* hr = hsT + k * 65 + nd_t * 4;
#pragma unroll
        for (int i = 0; i < 4; i++) {
            float h = hr[i];
            acc[i][0] = fmaf(h, w.x, acc[i][0]);
            acc[i][1] = fmaf(h, w.y, acc[i][1]);
            acc[i][2] = fmaf(h, w.z, acc[i][2]);
            acc[i][3] = fmaf(h, w.w, acc[i][3]);
        }
    }
#pragma unroll
    for (int i = 0; i < 4; i++) {
        int nd = n0 + nd_t * 4 + i;
        if (nd >= n) continue;
        size_t off = (size_t)nd * FO + fo0 + fo_t * 4;
        *reinterpret_cast<float4*>(tbuf + off) =
            make_float4(acc[i][0], acc[i][1], acc[i][2], acc[i][3]);
    }
}

// ---------------- per-dst gather: out[dst] = d2*t[dst] + sum norm*t[src] -----

template <int FO>
__global__ __launch_bounds__(256)
void k_gather(const float* __restrict__ t, float* __restrict__ out, int n) {
    constexpr int FO4 = FO / 4;
    int idx = blockIdx.x * 256 + threadIdx.x;
    if (idx >= n * FO4) return;
    int dst = idx / FO4;
    int c = idx - dst * FO4;
    const int r0 = g_off[dst], r1 = g_off[dst + 1];
    float d = g_deg[dst];
    float d2 = d * d;
    float4 sv = *reinterpret_cast<const float4*>(t + (size_t)dst * FO + c * 4);
    float ax = d2 * sv.x, ay = d2 * sv.y, az = d2 * sv.z, aw = d2 * sv.w;
    int j = r0;
    for (; j + 1 < r1; j += 2) {
        int s0 = g_csrc[j], s1 = g_csrc[j + 1];
        float m0 = g_cnorm[j], m1 = g_cnorm[j + 1];
        float4 v0 = *reinterpret_cast<const float4*>(t + (size_t)s0 * FO + c * 4);
        float4 v1 = *reinterpret_cast<const float4*>(t + (size_t)s1 * FO + c * 4);
        ax = fmaf(m0, v0.x, ax); ay = fmaf(m0, v0.y, ay);
        az = fmaf(m0, v0.z, az); aw = fmaf(m0, v0.w, aw);
        ax = fmaf(m1, v1.x, ax); ay = fmaf(m1, v1.y, ay);
        az = fmaf(m1, v1.z, az); aw = fmaf(m1, v1.w, aw);
    }
    if (j < r1) {
        int s0 = g_csrc[j];
        float m0 = g_cnorm[j];
        float4 v0 = *reinterpret_cast<const float4*>(t + (size_t)s0 * FO + c * 4);
        ax = fmaf(m0, v0.x, ax); ay = fmaf(m0, v0.y, ay);
        az = fmaf(m0, v0.z, az); aw = fmaf(m0, v0.w, aw);
    }
    *reinterpret_cast<float4*>(out + (size_t)dst * FO + c * 4) =
        make_float4(ax, ay, az, aw);
}

// ---------------- pooling ----------------

__global__ void k_zero_pool() {
    int i = blockIdx.x * blockDim.x + threadIdx.x;
    if (i < GG * 32) g_pool[i] = 0.f;
}

// block (32,8), each block covers 2048 nodes; batch sorted -> running max
__global__ void k_pool(const float* __restrict__ h, const float* __restrict__ b4,
                       const void* __restrict__ batch, int n) {
    const int tx = threadIdx.x;   // feature lane
    const int ty = threadIdx.y;   // node row
    const int base = blockIdx.x * 2048;
    const float bb = __ldg(&b4[tx]);
    const int is64 = g_is64;
    const long long* b64 = (const long long*)batch;
    const int* b32 = (const int*)batch;
    float rmax = 0.f;
    int curg = -1;
    for (int off = ty; off < 2048; off += 8) {
        int nd = base + off;
        if (nd >= n) break;
        int g = is64 ? (int)b64[nd] : b32[nd];
        float v = fmaxf(h[(size_t)nd * 32 + tx] + bb, 0.f);
        if (g != curg) {
            if (curg >= 0)
                atomicMax(reinterpret_cast<int*>(&g_pool[curg * 32 + tx]),
                          __float_as_int(rmax));
            curg = g;
            rmax = v;
        } else {
            rmax = fmaxf(rmax, v);
        }
    }
    if (curg >= 0)
        atomicMax(reinterpret_cast<int*>(&g_pool[curg * 32 + tx]),
                  __float_as_int(rmax));
}

// ---------------- final MLP: relu(g@W5+b5)@W6+b6 ----------------

__global__ void k_mlp(const float* __restrict__ W5, const float* __restrict__ b5,
                      const float* __restrict__ W6, const float* __restrict__ b6,
                      float* __restrict__ out) {
    __shared__ float W5s[32 * 32], b5s[32], W6s[64], b6s[2];
    int t = threadIdx.x;   // 64 threads = 64 graphs
    for (int i = t; i < 1024; i += 64) W5s[i] = W5[i];
    if (t < 32) b5s[t] = b5[t];
    W6s[t] = W6[t];
    if (t < 2) b6s[t] = b6[t];
    __syncthreads();
    float p[32];
#pragma unroll
    for (int k = 0; k < 32; k++) p[k] = g_pool[t * 32 + k];
    float o0 = b6s[0], o1 = b6s[1];
#pragma unroll 4
    for (int j = 0; j < 32; j++) {
        float s = b5s[j];
#pragma unroll
        for (int k = 0; k < 32; k++) s = fmaf(p[k], W5s[k * 32 + j], s);
        s = fmaxf(s, 0.f);
        o0 = fmaf(s, W6s[j * 2], o0);
        o1 = fmaf(s, W6s[j * 2 + 1], o1);
    }
    out[t * 2] = o0;
    out[t * 2 + 1] = o1;
}

// ---------------- launch ----------------

extern "C" void kernel_launch(void* const* d_in, const int* in_sizes, int n_in,
                              void* d_out, int out_size) {
    const float* x  = (const float*)d_in[0];
    const void*  ei = d_in[1];
    const float* ew = (const float*)d_in[2];
    const void*  bt = d_in[3];
    const float* W1 = (const float*)d_in[4];
    const float* b1 = (const float*)d_in[5];
    const float* W2 = (const float*)d_in[6];
    const float* b2 = (const float*)d_in[7];
    const float* W3 = (const float*)d_in[8];
    const float* b3 = (const float*)d_in[9];
    const float* W4 = (const float*)d_in[10];
    const float* b4 = (const float*)d_in[11];
    const float* W5 = (const float*)d_in[12];
    const float* b5 = (const float*)d_in[13];
    const float* W6 = (const float*)d_in[14];
    const float* b6 = (const float*)d_in[15];
    float* out = (float*)d_out;

    const int n = in_sizes[0];
    const int e = in_sizes[2];

    const int nb  = (n + 255) / 256;
    const int ebk = (e + 255) / 256;
    const int nchunks = (n + 1023) / 1024;

    k_detect<<<1, 256>>>((const int*)ei);
    k_init<<<nb, 256>>>(n);
    k_edges_pre<<<ebk, 256>>>(ei, ew, e);
    k_scan1<<<nchunks, 1024>>>(n);
    k_scan2<<<1, 1024>>>(nchunks);
    k_scan3<<<nb, 256>>>(n);
    k_dis<<<nb, 256>>>(n);
    k_norm_fill<<<ebk, 256>>>(ew, e);

    // layer 1: gather x -> ax
    k_gather_ax<<<nb, 256>>>(x, n);

    const int gx = (n + 63) / 64;

    float* A; float* B; float* C;
    cudaGetSymbolAddress((void**)&A, g_A);
    cudaGetSymbolAddress((void**)&B, g_B);
    cudaGetSymbolAddress((void**)&C, g_C);

    // layer 2 (fused layer-1 expand): t2->B, gather -> C
    k_gemm2<<<dim3(gx, 3), 128>>>(W1, b1, W2, B, n);
    k_gather<96><<<(n * 24 + 255) / 256, 256>>>(B, C, n);

    // layer 3: in C (+b2,relu) -> t3->A, gather -> B
    k_gemm<96, 64><<<dim3(gx, 2), 128>>>(C, b2, W3, A, n);
    k_gather<64><<<(n * 16 + 255) / 256, 256>>>(A, B, n);

    // layer 4: in B (+b3,relu) -> t4->C, gather -> A
    k_gemm<64, 32><<<dim3(gx, 1), 128>>>(B, b3, W4, C, n);
    k_gather<32><<<(n * 8 + 255) / 256, 256>>>(C, A, n);

    // pool + MLP
    k_zero_pool<<<8, 256>>>();
    k_pool<<<(n + 2047) / 2048, dim3(32, 8)>>>(A, b4, bt, n);
    k_mlp<<<1, 64>>>(W5, b5, W6, b6, out);
}